// round 10
// baseline (speedup 1.0000x reference)
#include <cuda_runtime.h>
#include <cuda_bf16.h>

// AttentionRouting: u [B=4, I=32, N=32, J=16, H=32, W=32] f32, bias [1,32,32,1,1,1]
//   v = sum_i u; c_raw = sum_j u*v; c = softmax_n(0.25*c_raw) + bias
//   s = sum_i u*c; squash over j.
//
// R9: K1 occupancy push — j-groups of 4 (16 live regs vs 32),
// __launch_bounds__(256,6) -> 6 CTAs/SM (75% occ). One shfl level/j,
// 32-thread stage-2, 8 barriers/CTA. K2/K3 as R8.

#define BB 4
#define II 32
#define NN 32
#define JJ 16
#define HH 32
#define WW 32
#define HW 1024
#define STRIDE_I 524288   // N*J*H*W

// scratch: c_raw [B,I,N,H,W] 16MB, lse [B,I,H,W] 512KB
__device__ float g_craw[BB * II * NN * HW];
__device__ float g_lse[BB * II * HW];

// ---------------------------------------------------------------------------
// K1: CTA = (b,n,h). 256 threads: i = tid>>3, q = tid&7 (w float4-chunk).
// ---------------------------------------------------------------------------
__global__ void __launch_bounds__(256, 6) k1_craw(const float* __restrict__ u) {
    __shared__ float4 vpart[8][2][4][8];           // [warp][half][jl][q] 8 KB
    __shared__ float v_s[4][32];                   // 512 B

    const int bid = blockIdx.x;                    // (b*NN + n)*HH + h
    const int h = bid & 31;
    const int n = (bid >> 5) & 31;
    const int b = bid >> 10;
    const int tid = threadIdx.x;
    const int lane = tid & 31;
    const int warp = tid >> 5;
    const int q = lane & 7;
    const int iA = lane >> 3;                      // 0..3
    const int i = warp * 4 + iA;                   // 0..31

    const float* up = u + ((size_t)((b * II + i) * NN + n)) * (JJ * HW)
                        + h * WW + q * 4;

    float4 cacc = make_float4(0.f, 0.f, 0.f, 0.f);

#pragma unroll
    for (int g = 0; g < 4; g++) {
        // front-batched loads: 4 independent LDG.128
        float4 r[4];
#pragma unroll
        for (int jl = 0; jl < 4; jl++)
            r[jl] = *(const float4*)(up + (g * 4 + jl) * HW);

        // stage 1: ONE xor level — halves iA={0,1},{2,3}
#pragma unroll
        for (int jl = 0; jl < 4; jl++) {
            float4 vp = r[jl];
            vp.x += __shfl_xor_sync(0xffffffffu, vp.x, 8);
            vp.y += __shfl_xor_sync(0xffffffffu, vp.y, 8);
            vp.z += __shfl_xor_sync(0xffffffffu, vp.z, 8);
            vp.w += __shfl_xor_sync(0xffffffffu, vp.w, 8);
            if ((iA & 1) == 0) vpart[warp][iA >> 1][jl][q] = vp;
        }
        __syncthreads();

        // stage 2: 32 threads combine 8 warps x 2 halves -> v_s[jl][w]
        if (tid < 32) {
            const int j2 = tid >> 3, q2 = tid & 7;
            float4 a = make_float4(0.f, 0.f, 0.f, 0.f);
#pragma unroll
            for (int wg = 0; wg < 8; wg++) {
#pragma unroll
                for (int hh = 0; hh < 2; hh++) {
                    const float4 x = vpart[wg][hh][j2][q2];
                    a.x += x.x; a.y += x.y; a.z += x.z; a.w += x.w;
                }
            }
            *(float4*)&v_s[j2][q2 * 4] = a;
        }
        __syncthreads();

        // compute: cacc += u_reg * v (broadcast LDS.128)
#pragma unroll
        for (int jl = 0; jl < 4; jl++) {
            const float4 v4 = *(const float4*)&v_s[jl][q * 4];
            cacc.x += r[jl].x * v4.x;
            cacc.y += r[jl].y * v4.y;
            cacc.z += r[jl].z * v4.z;
            cacc.w += r[jl].w * v4.w;
        }
    }

    *(float4*)(g_craw + ((size_t)((b * II + i) * NN + n)) * HW
               + h * WW + q * 4) = cacc;
}

// ---------------------------------------------------------------------------
// K2: per-pixel (b,i,h,w) log-sum-exp over n of 0.25*c_raw.
// ---------------------------------------------------------------------------
__global__ void __launch_bounds__(256) k2_lse() {
    const int t = blockIdx.x * 256 + threadIdx.x;  // 0..131071
    const int hw = t & 1023;
    const int bi = t >> 10;                        // b*II + i
    const float* p = g_craw + bi * (NN * HW) + hw;

    float vals[NN];
    float m = -3.402823466e+38f;
#pragma unroll
    for (int n = 0; n < NN; n++) {
        vals[n] = 0.25f * p[n * HW];
        m = fmaxf(m, vals[n]);
    }
    float s = 0.f;
#pragma unroll
    for (int n = 0; n < NN; n++) s += expf(vals[n] - m);
    g_lse[t] = m + logf(s);
}

// ---------------------------------------------------------------------------
// K3: per (b, n, h) slice, 512 threads (j,w). (b,n) REVERSED so early CTAs
// hit the u tail K1 left in L2.
// ---------------------------------------------------------------------------
__global__ void __launch_bounds__(512) k3_out(const float* __restrict__ u,
                                             const float* __restrict__ bias,
                                             float* __restrict__ out) {
    __shared__ float c_s[II * WW];                 // 4 KB
    __shared__ float s_s[JJ * WW];                 // 2 KB

    const int bid = blockIdx.x;                    // reversed mapping
    const int h = bid & 31;
    const int n = 31 - ((bid >> 5) & 31);
    const int b = (BB - 1) - (bid >> 10);
    const int tid = threadIdx.x;

#pragma unroll
    for (int t = tid; t < II * WW; t += 512) {
        const int i = t >> 5;
        const int w = t & 31;
        const int hw = h * WW + w;
        const float cr = g_craw[((b * II + i) * NN + n) * HW + hw];
        const float lse = g_lse[(b * II + i) * HW + hw];
        c_s[t] = expf(0.25f * cr - lse) + __ldg(&bias[i * NN + n]);
    }
    __syncthreads();

    const int jj = tid >> 5;                       // 0..15
    const int w = tid & 31;
    const int base = (b * 1024 + n) * (JJ * HW) + h * WW + w + jj * HW;

    float a0 = 0.f, a1 = 0.f, a2 = 0.f, a3 = 0.f;
#pragma unroll
    for (int i = 0; i < II; i += 4) {
        a0 += u[base + (i + 0) * STRIDE_I] * c_s[(i + 0) * 32 + w];
        a1 += u[base + (i + 1) * STRIDE_I] * c_s[(i + 1) * 32 + w];
        a2 += u[base + (i + 2) * STRIDE_I] * c_s[(i + 2) * 32 + w];
        a3 += u[base + (i + 3) * STRIDE_I] * c_s[(i + 3) * 32 + w];
    }
    const float acc = (a0 + a1) + (a2 + a3);

    s_s[tid] = acc;
    __syncthreads();

    float nrm2 = 0.f;
#pragma unroll
    for (int j2 = 0; j2 < JJ; j2++) {
        const float x = s_s[j2 * WW + w];
        nrm2 += x * x;
    }
    const float nrm = sqrtf(nrm2);
    const float factor =
        (1.0f - 1.0f / (expf(nrm) + 1e-20f)) / (nrm + 1e-20f);

    out[((b * NN + n) * JJ + jj) * HW + h * WW + w] = acc * factor;
}

// ---------------------------------------------------------------------------
extern "C" void kernel_launch(void* const* d_in, const int* in_sizes, int n_in,
                              void* d_out, int out_size) {
    const float* u = (const float*)d_in[0];
    const float* bias = (const float*)d_in[1];
    float* out = (float*)d_out;

    k1_craw<<<BB * NN * HH, 256>>>(u);             // 4096 CTAs
    k2_lse<<<(BB * II * HW) / 256, 256>>>();       // 512 CTAs
    k3_out<<<BB * NN * HH, 512>>>(u, bias, out);   // 4096 CTAs
}

// round 13
// speedup vs baseline: 1.2009x; 1.2009x over previous
#include <cuda_runtime.h>
#include <cuda_bf16.h>
#include <cuda_pipeline.h>
#include <cstdint>

// AttentionRouting: u [B=4, I=32, N=32, J=16, H=32, W=32] f32, bias [1,32,32,1,1,1]
//   v = sum_i u; c_raw = sum_j u*v; c = softmax_n(0.25*c_raw) + bias
//   s = sum_i u*c; squash over j.
//
// R10 design, third submission: K1 via cp.async (now through cuda_pipeline.h
// intrinsics instead of inline PTX — identical LDGSTS codegen, supported
// toolchain path). Whole 64KB (b,n,h) slice streamed to smem with no register
// pressure and no mid-stream barriers; both reductions from smem, lane=w
// conflict-free. 0 shuffles, 2 barriers. K2/K3 as R8 (best).

#define BB 4
#define II 32
#define NN 32
#define JJ 16
#define HH 32
#define WW 32
#define HW 1024
#define STRIDE_I 524288   // N*J*H*W

// scratch: c_raw [B,I,N,H,W] 16MB, lse [B,I,H,W] 512KB
__device__ float g_craw[BB * II * NN * HW];
__device__ float g_lse[BB * II * HW];

// ---------------------------------------------------------------------------
// K1: CTA = (b,n,h). 256 threads. Dynamic smem u_s[32][16][32] = 64KB.
// ---------------------------------------------------------------------------
__global__ void __launch_bounds__(256) k1_craw(const float* __restrict__ u) {
    extern __shared__ float u_s[];                 // [i*512 + j*32 + w]
    __shared__ float v_s[JJ * WW];                 // 2 KB

    const int bid = blockIdx.x;                    // (b*NN + n)*HH + h
    const int h = bid & 31;
    const int n = (bid >> 5) & 31;
    const int b = bid >> 10;
    const int tid = threadIdx.x;
    const int lane = tid & 31;

    // ---- cp.async: stream slice. thread (i = tid>>3, q = tid&7) ----
    {
        const int i = tid >> 3;
        const int q = tid & 7;
        const float* up = u + ((size_t)((b * II + i) * NN + n)) * (JJ * HW)
                            + h * WW + q * 4;
        float* dst = u_s + i * 512 + q * 4;
#pragma unroll
        for (int j = 0; j < JJ; j++) {
            __pipeline_memcpy_async(dst + j * 32, up + j * HW, 16);
        }
        __pipeline_commit();
        __pipeline_wait_prior(0);
    }
    __syncthreads();

    // ---- phase 1: v[j][w] = sum_i u_s[i][j][w]. thread (jl = tid>>5, w) ----
    {
        const int jl = tid >> 5;                   // 0..7
#pragma unroll
        for (int rep = 0; rep < 2; rep++) {
            const int j = jl + rep * 8;
            float a0 = 0.f, a1 = 0.f, a2 = 0.f, a3 = 0.f;
#pragma unroll
            for (int i2 = 0; i2 < II; i2 += 4) {
                a0 += u_s[(i2 + 0) * 512 + j * 32 + lane];
                a1 += u_s[(i2 + 1) * 512 + j * 32 + lane];
                a2 += u_s[(i2 + 2) * 512 + j * 32 + lane];
                a3 += u_s[(i2 + 3) * 512 + j * 32 + lane];
            }
            v_s[j * 32 + lane] = (a0 + a1) + (a2 + a3);
        }
    }
    __syncthreads();

    // ---- phase 2: c_raw[i][w] = sum_j u_s[i][j][w] * v[j][w] ----
    {
        float vreg[JJ];
#pragma unroll
        for (int j = 0; j < JJ; j++) vreg[j] = v_s[j * 32 + lane];

        const int i0 = tid >> 5;                   // 0..7
#pragma unroll
        for (int m = 0; m < 4; m++) {
            const int i = i0 + 8 * m;
            float a0 = 0.f, a1 = 0.f;
#pragma unroll
            for (int j = 0; j < JJ; j += 2) {
                a0 += u_s[i * 512 + (j + 0) * 32 + lane] * vreg[j + 0];
                a1 += u_s[i * 512 + (j + 1) * 32 + lane] * vreg[j + 1];
            }
            g_craw[((size_t)((b * II + i) * NN + n)) * HW + h * WW + lane] =
                a0 + a1;
        }
    }
}

// ---------------------------------------------------------------------------
// K2: per-pixel (b,i,h,w) log-sum-exp over n of 0.25*c_raw.
// ---------------------------------------------------------------------------
__global__ void __launch_bounds__(256) k2_lse() {
    const int t = blockIdx.x * 256 + threadIdx.x;  // 0..131071
    const int hw = t & 1023;
    const int bi = t >> 10;                        // b*II + i
    const float* p = g_craw + bi * (NN * HW) + hw;

    float vals[NN];
    float m = -3.402823466e+38f;
#pragma unroll
    for (int n = 0; n < NN; n++) {
        vals[n] = 0.25f * p[n * HW];
        m = fmaxf(m, vals[n]);
    }
    float s = 0.f;
#pragma unroll
    for (int n = 0; n < NN; n++) s += expf(vals[n] - m);
    g_lse[t] = m + logf(s);
}

// ---------------------------------------------------------------------------
// K3: per (b, n, h) slice, 512 threads (j,w). (b,n) REVERSED so early CTAs
// hit the u tail K1 left in L2.
// ---------------------------------------------------------------------------
__global__ void __launch_bounds__(512) k3_out(const float* __restrict__ u,
                                             const float* __restrict__ bias,
                                             float* __restrict__ out) {
    __shared__ float c_s[II * WW];                 // 4 KB
    __shared__ float s_s[JJ * WW];                 // 2 KB

    const int bid = blockIdx.x;                    // reversed mapping
    const int h = bid & 31;
    const int n = 31 - ((bid >> 5) & 31);
    const int b = (BB - 1) - (bid >> 10);
    const int tid = threadIdx.x;

#pragma unroll
    for (int t = tid; t < II * WW; t += 512) {
        const int i = t >> 5;
        const int w = t & 31;
        const int hw = h * WW + w;
        const float cr = g_craw[((b * II + i) * NN + n) * HW + hw];
        const float lse = g_lse[(b * II + i) * HW + hw];
        c_s[t] = expf(0.25f * cr - lse) + __ldg(&bias[i * NN + n]);
    }
    __syncthreads();

    const int jj = tid >> 5;                       // 0..15
    const int w = tid & 31;
    const int base = (b * 1024 + n) * (JJ * HW) + h * WW + w + jj * HW;

    float a0 = 0.f, a1 = 0.f, a2 = 0.f, a3 = 0.f;
#pragma unroll
    for (int i = 0; i < II; i += 4) {
        a0 += u[base + (i + 0) * STRIDE_I] * c_s[(i + 0) * 32 + w];
        a1 += u[base + (i + 1) * STRIDE_I] * c_s[(i + 1) * 32 + w];
        a2 += u[base + (i + 2) * STRIDE_I] * c_s[(i + 2) * 32 + w];
        a3 += u[base + (i + 3) * STRIDE_I] * c_s[(i + 3) * 32 + w];
    }
    const float acc = (a0 + a1) + (a2 + a3);

    s_s[tid] = acc;
    __syncthreads();

    float nrm2 = 0.f;
#pragma unroll
    for (int j2 = 0; j2 < JJ; j2++) {
        const float x = s_s[j2 * WW + w];
        nrm2 += x * x;
    }
    const float nrm = sqrtf(nrm2);
    const float factor =
        (1.0f - 1.0f / (expf(nrm) + 1e-20f)) / (nrm + 1e-20f);

    out[((b * NN + n) * JJ + jj) * HW + h * WW + w] = acc * factor;
}

// ---------------------------------------------------------------------------
extern "C" void kernel_launch(void* const* d_in, const int* in_sizes, int n_in,
                              void* d_out, int out_size) {
    const float* u = (const float*)d_in[0];
    const float* bias = (const float*)d_in[1];
    float* out = (float*)d_out;

    cudaFuncSetAttribute(k1_craw, cudaFuncAttributeMaxDynamicSharedMemorySize,
                         II * JJ * WW * (int)sizeof(float));   // 65536 B

    k1_craw<<<BB * NN * HH, 256, II * JJ * WW * sizeof(float)>>>(u);
    k2_lse<<<(BB * II * HW) / 256, 256>>>();       // 512 CTAs
    k3_out<<<BB * NN * HH, 512>>>(u, bias, out);   // 4096 CTAs
}

// round 14
// speedup vs baseline: 1.2330x; 1.0268x over previous
#include <cuda_runtime.h>
#include <cuda_bf16.h>
#include <cuda_pipeline.h>
#include <cstdint>

// AttentionRouting: u [B=4, I=32, N=32, J=16, H=32, W=32] f32, bias [1,32,32,1,1,1]
//   v = sum_i u; c_raw = sum_j u*v; c = softmax_n(0.25*c_raw) + bias
//   s = sum_i u*c; squash over j.
//
// R14: overlap load & compute.
//  K1: cp.async in two j-half groups; phase-1a on group A overlaps group B's
//      in-flight stream. 3 barriers.
//  K3: cp.async full u slice first, c_s prologue (craw/lse/exp) computed
//      during the stream, then s from smem with c in registers. Reversed
//      (b,n) kept for L2 tail reuse. K2 unchanged.

#define BB 4
#define II 32
#define NN 32
#define JJ 16
#define HH 32
#define WW 32
#define HW 1024
#define STRIDE_I 524288   // N*J*H*W

// scratch: c_raw [B,I,N,H,W] 16MB, lse [B,I,H,W] 512KB
__device__ float g_craw[BB * II * NN * HW];
__device__ float g_lse[BB * II * HW];

// ---------------------------------------------------------------------------
// K1: CTA = (b,n,h). 256 threads. Dynamic smem u_s[32][16][32] = 64KB.
// ---------------------------------------------------------------------------
__global__ void __launch_bounds__(256) k1_craw(const float* __restrict__ u) {
    extern __shared__ float u_s[];                 // [i*512 + j*32 + w]
    __shared__ float v_s[JJ * WW];                 // 2 KB

    const int bid = blockIdx.x;                    // (b*NN + n)*HH + h
    const int h = bid & 31;
    const int n = (bid >> 5) & 31;
    const int b = bid >> 10;
    const int tid = threadIdx.x;
    const int lane = tid & 31;

    // ---- cp.async: two committed groups (j 0-7, j 8-15) ----
    {
        const int i = tid >> 3;
        const int q = tid & 7;
        const float* up = u + ((size_t)((b * II + i) * NN + n)) * (JJ * HW)
                            + h * WW + q * 4;
        float* dst = u_s + i * 512 + q * 4;
#pragma unroll
        for (int j = 0; j < 8; j++)
            __pipeline_memcpy_async(dst + j * 32, up + j * HW, 16);
        __pipeline_commit();
#pragma unroll
        for (int j = 8; j < 16; j++)
            __pipeline_memcpy_async(dst + j * 32, up + j * HW, 16);
        __pipeline_commit();
    }

    const int jl = tid >> 5;                       // 0..7

    // ---- phase 1a: v for j=0..7 while group B still streams ----
    __pipeline_wait_prior(1);
    __syncthreads();
    {
        const int j = jl;
        float a0 = 0.f, a1 = 0.f, a2 = 0.f, a3 = 0.f;
#pragma unroll
        for (int i2 = 0; i2 < II; i2 += 4) {
            a0 += u_s[(i2 + 0) * 512 + j * 32 + lane];
            a1 += u_s[(i2 + 1) * 512 + j * 32 + lane];
            a2 += u_s[(i2 + 2) * 512 + j * 32 + lane];
            a3 += u_s[(i2 + 3) * 512 + j * 32 + lane];
        }
        v_s[j * 32 + lane] = (a0 + a1) + (a2 + a3);
    }

    // ---- phase 1b: v for j=8..15 ----
    __pipeline_wait_prior(0);
    __syncthreads();
    {
        const int j = jl + 8;
        float a0 = 0.f, a1 = 0.f, a2 = 0.f, a3 = 0.f;
#pragma unroll
        for (int i2 = 0; i2 < II; i2 += 4) {
            a0 += u_s[(i2 + 0) * 512 + j * 32 + lane];
            a1 += u_s[(i2 + 1) * 512 + j * 32 + lane];
            a2 += u_s[(i2 + 2) * 512 + j * 32 + lane];
            a3 += u_s[(i2 + 3) * 512 + j * 32 + lane];
        }
        v_s[j * 32 + lane] = (a0 + a1) + (a2 + a3);
    }
    __syncthreads();

    // ---- phase 2: c_raw[i][w] = sum_j u_s[i][j][w] * v[j][w] ----
    {
        float vreg[JJ];
#pragma unroll
        for (int j = 0; j < JJ; j++) vreg[j] = v_s[j * 32 + lane];

        const int i0 = tid >> 5;                   // 0..7
#pragma unroll
        for (int m = 0; m < 4; m++) {
            const int i = i0 + 8 * m;
            float a0 = 0.f, a1 = 0.f;
#pragma unroll
            for (int j = 0; j < JJ; j += 2) {
                a0 += u_s[i * 512 + (j + 0) * 32 + lane] * vreg[j + 0];
                a1 += u_s[i * 512 + (j + 1) * 32 + lane] * vreg[j + 1];
            }
            g_craw[((size_t)((b * II + i) * NN + n)) * HW + h * WW + lane] =
                a0 + a1;
        }
    }
}

// ---------------------------------------------------------------------------
// K2: per-pixel (b,i,h,w) log-sum-exp over n of 0.25*c_raw.
// ---------------------------------------------------------------------------
__global__ void __launch_bounds__(256) k2_lse() {
    const int t = blockIdx.x * 256 + threadIdx.x;  // 0..131071
    const int hw = t & 1023;
    const int bi = t >> 10;                        // b*II + i
    const float* p = g_craw + bi * (NN * HW) + hw;

    float vals[NN];
    float m = -3.402823466e+38f;
#pragma unroll
    for (int n = 0; n < NN; n++) {
        vals[n] = 0.25f * p[n * HW];
        m = fmaxf(m, vals[n]);
    }
    float s = 0.f;
#pragma unroll
    for (int n = 0; n < NN; n++) s += expf(vals[n] - m);
    g_lse[t] = m + logf(s);
}

// ---------------------------------------------------------------------------
// K3: CTA = (b,n,h) reversed, 256 threads. cp.async u slice overlapped with
// c_s prologue; s computed from smem with c in registers; squash; store.
// Dynamic smem: u 64KB + c 4KB + s 2KB = 71680 B.
// ---------------------------------------------------------------------------
__global__ void __launch_bounds__(256) k3_out(const float* __restrict__ u,
                                             const float* __restrict__ bias,
                                             float* __restrict__ out) {
    extern __shared__ float sm[];
    float* u_s = sm;                               // [i*512 + j*32 + w]
    float* c_s = sm + 16384;                       // [i*32 + w]
    float* s_s = sm + 17408;                       // [j*32 + w]

    const int bid = blockIdx.x;                    // reversed mapping
    const int h = bid & 31;
    const int n = 31 - ((bid >> 5) & 31);
    const int b = (BB - 1) - (bid >> 10);
    const int tid = threadIdx.x;
    const int lane = tid & 31;

    // ---- cp.async u slice (fire-and-forget) ----
    {
        const int i = tid >> 3;
        const int q = tid & 7;
        const float* up = u + ((size_t)((b * II + i) * NN + n)) * (JJ * HW)
                            + h * WW + q * 4;
        float* dst = u_s + i * 512 + q * 4;
#pragma unroll
        for (int j = 0; j < JJ; j++)
            __pipeline_memcpy_async(dst + j * 32, up + j * HW, 16);
        __pipeline_commit();
    }

    // ---- c_s prologue during the stream ----
    {
        const int i0 = tid >> 5;                   // 0..7
        const int hw = h * WW + lane;
#pragma unroll
        for (int m = 0; m < 4; m++) {
            const int i = i0 + 8 * m;
            const float cr = g_craw[((size_t)((b * II + i) * NN + n)) * HW + hw];
            const float lse = g_lse[(b * II + i) * HW + hw];
            c_s[i * 32 + lane] = expf(0.25f * cr - lse)
                                 + __ldg(&bias[i * NN + n]);
        }
    }
    __pipeline_wait_prior(0);
    __syncthreads();

    // ---- s[j][w] = sum_i u_s[i][j][w] * c[i][w], c in registers ----
    float creg[II];
#pragma unroll
    for (int i = 0; i < II; i++) creg[i] = c_s[i * 32 + lane];

    const int j0 = tid >> 5;                       // 0..7
    float sv[2];
#pragma unroll
    for (int r = 0; r < 2; r++) {
        const int j = j0 + 8 * r;
        float a0 = 0.f, a1 = 0.f, a2 = 0.f, a3 = 0.f;
#pragma unroll
        for (int i = 0; i < II; i += 4) {
            a0 += u_s[(i + 0) * 512 + j * 32 + lane] * creg[i + 0];
            a1 += u_s[(i + 1) * 512 + j * 32 + lane] * creg[i + 1];
            a2 += u_s[(i + 2) * 512 + j * 32 + lane] * creg[i + 2];
            a3 += u_s[(i + 3) * 512 + j * 32 + lane] * creg[i + 3];
        }
        sv[r] = (a0 + a1) + (a2 + a3);
        s_s[j * 32 + lane] = sv[r];
    }
    __syncthreads();

    // ---- squash over j, store ----
    float nrm2 = 0.f;
#pragma unroll
    for (int j2 = 0; j2 < JJ; j2++) {
        const float x = s_s[j2 * 32 + lane];
        nrm2 += x * x;
    }
    const float nrm = sqrtf(nrm2);
    const float factor =
        (1.0f - 1.0f / (expf(nrm) + 1e-20f)) / (nrm + 1e-20f);

#pragma unroll
    for (int r = 0; r < 2; r++) {
        const int j = j0 + 8 * r;
        out[((size_t)(b * NN + n) * JJ + j) * HW + h * WW + lane] =
            sv[r] * factor;
    }
}

// ---------------------------------------------------------------------------
extern "C" void kernel_launch(void* const* d_in, const int* in_sizes, int n_in,
                              void* d_out, int out_size) {
    const float* u = (const float*)d_in[0];
    const float* bias = (const float*)d_in[1];
    float* out = (float*)d_out;

    cudaFuncSetAttribute(k1_craw, cudaFuncAttributeMaxDynamicSharedMemorySize,
                         II * JJ * WW * (int)sizeof(float));     // 65536 B
    cudaFuncSetAttribute(k3_out, cudaFuncAttributeMaxDynamicSharedMemorySize,
                         17920 * (int)sizeof(float));            // 71680 B

    k1_craw<<<BB * NN * HH, 256, II * JJ * WW * sizeof(float)>>>(u);
    k2_lse<<<(BB * II * HW) / 256, 256>>>();       // 512 CTAs
    k3_out<<<BB * NN * HH, 256, 17920 * sizeof(float)>>>(u, bias, out);
}